// round 15
// baseline (speedup 1.0000x reference)
#include <cuda_runtime.h>
#include <cuda_fp16.h>
#include <cstdint>
#include <cstdio>

#define SEQ 2048
#define DIM 4096
#define NH 32
#define NKV 8
#define HD 128
#define KVD (NKV*HD)   // 1024

// fp16 operands (no fp32 intermediates)
__device__ __half g_qh[SEQ * DIM];       // 16 MB (rope fused in proj epilogue, pair-permuted)
__device__ __half g_kh[SEQ * KVD];       // 4 MB
__device__ __half g_vT[KVD * SEQ];       // 4 MB  (V transposed: [head col][seq])
__device__ __half g_attnh[SEQ * DIM];    // 16 MB (attn out, pair-permuted)
__device__ __half g_xh[SEQ * DIM];       // 16 MB (prep: fp16 + pair-permute)
__device__ __half g_wqh[DIM * DIM];      // 32 MB
__device__ __half g_wkh[KVD * DIM];      // 8 MB
__device__ __half g_wvh[KVD * DIM];      // 8 MB
__device__ __half g_woh[DIM * DIM];      // 32 MB
__device__ float2 g_tab[SEQ * 64];       // 1 MB rope cos/sin table

__device__ __forceinline__ void mma_f16(float* d,
                                        uint32_t a0, uint32_t a1, uint32_t a2, uint32_t a3,
                                        uint32_t b0, uint32_t b1) {
    asm volatile(
        "mma.sync.aligned.m16n8k16.row.col.f32.f16.f16.f32 "
        "{%0,%1,%2,%3}, {%4,%5,%6,%7}, {%8,%9}, {%0,%1,%2,%3};"
        : "+f"(d[0]), "+f"(d[1]), "+f"(d[2]), "+f"(d[3])
        : "r"(a0), "r"(a1), "r"(a2), "r"(a3), "r"(b0), "r"(b1));
}

__device__ __forceinline__ void cp_async16(uint32_t smem_addr, const void* gptr) {
    asm volatile("cp.async.cg.shared.global [%0], [%1], 16;"
                 :: "r"(smem_addr), "l"(gptr) : "memory");
}
#define CP_COMMIT() asm volatile("cp.async.commit_group;" ::: "memory")
#define CP_WAIT(n)  asm volatile("cp.async.wait_group %0;" :: "n"(n) : "memory")

__device__ __forceinline__ uint32_t smem_u32(const void* p) {
    uint32_t a;
    asm("{ .reg .u64 t; cvta.to.shared.u64 t, %1; cvt.u32.u64 %0, t; }" : "=r"(a) : "l"(p));
    return a;
}

// ---------------------------------------------------------------------------
// RoPE cos/sin table
// ---------------------------------------------------------------------------
__global__ void tab_kernel() {
    int idx = blockIdx.x * blockDim.x + threadIdx.x;
    if (idx >= SEQ * 64) return;
    int i = idx & 63, s = idx >> 6;
    float freq = exp2f(-(float)i * (18.931568569324174f / 64.0f));
    float ang = (float)s * freq;
    float sn, cs;
    sincosf(ang, &sn, &cs);
    g_tab[idx] = make_float2(cs, sn);
}

// ---------------------------------------------------------------------------
// Merged prep: fp32 -> fp16 with pair-permute within each 16-el k-group.
// ---------------------------------------------------------------------------
#define NG_X  (SEQ * DIM / 16)
#define NG_WQ (DIM * DIM / 16)
#define NG_WK (KVD * DIM / 16)
#define B0 NG_X
#define B1 (B0 + NG_WQ)
#define B2 (B1 + NG_WK)
#define B3 (B2 + NG_WK)
#define B4 (B3 + NG_WQ)

__global__ void prep_all_kernel(const float* __restrict__ x,  const float* __restrict__ wq,
                                const float* __restrict__ wk, const float* __restrict__ wv,
                                const float* __restrict__ wo) {
    long g = (long)blockIdx.x * blockDim.x + threadIdx.x;
    if (g >= B4) return;
    const float* src; __half* dst; long l;
    if (g < B0)      { src = x;  dst = g_xh;  l = g; }
    else if (g < B1) { src = wq; dst = g_wqh; l = g - B0; }
    else if (g < B2) { src = wk; dst = g_wkh; l = g - B1; }
    else if (g < B3) { src = wv; dst = g_wvh; l = g - B2; }
    else             { src = wo; dst = g_woh; l = g - B3; }

    const float4* s = (const float4*)src + l * 4;
    float4 f0 = s[0], f1 = s[1], f2 = s[2], f3 = s[3];
    __half2* d = (__half2*)dst + l * 8;
    d[0] = __floats2half2_rn(f0.x, f0.y);
    d[1] = __floats2half2_rn(f2.x, f2.y);
    d[2] = __floats2half2_rn(f0.z, f0.w);
    d[3] = __floats2half2_rn(f2.z, f2.w);
    d[4] = __floats2half2_rn(f1.x, f1.y);
    d[5] = __floats2half2_rn(f3.x, f3.y);
    d[6] = __floats2half2_rn(f1.z, f1.w);
    d[7] = __floats2half2_rn(f3.z, f3.w);
}

// ---------------------------------------------------------------------------
// fp16 GEMM core (unchanged): CTA 128x128, 4 warps 64x64, KC 32,
// 4-stage cp.async ring. modes: 0 fp32; 1 V^T fp16; 2/3 rope-fused fp16 Q/K.
// ---------------------------------------------------------------------------
#define KC 32
#define STG_B (128 * 96)
#define GEMM_SMEM (8 * STG_B)            // 98304 B

__device__ __forceinline__ void gemm_body(
    const __half* __restrict__ A, const __half* __restrict__ B,
    float* __restrict__ C, int N, int K, int mode,
    int bm, int bn, char* smem)
{
    char* As[4]; char* Bs[4];
#pragma unroll
    for (int s = 0; s < 4; s++) {
        As[s] = smem + s * 2 * STG_B;
        Bs[s] = As[s] + STG_B;
    }

    const int tid  = threadIdx.x;
    const int warp = tid >> 5, lane = tid & 31;
    const int gid  = lane >> 2, tig = lane & 3;
    const int wm   = warp >> 1, wn = warp & 1;

    const __half* Ab = A + (size_t)(bm * 128) * K;
    const __half* Bb = B + (size_t)(bn * 128) * K;

    auto issue = [&](int kt, int s) {
        const __half* Ak = Ab + kt * KC;
        const __half* Bk = Bb + kt * KC;
        uint32_t as = smem_u32(As[s]);
        uint32_t bs = smem_u32(Bs[s]);
#pragma unroll
        for (int i = 0; i < 4; i++) {
            int idx = tid + i * 128;
            int r = idx >> 2, c = idx & 3;
            cp_async16(as + r * 96 + c * 16, Ak + (size_t)r * K + c * 8);
        }
#pragma unroll
        for (int i = 0; i < 4; i++) {
            int idx = tid + i * 128;
            int r = idx >> 2, c = idx & 3;
            cp_async16(bs + r * 96 + c * 16, Bk + (size_t)r * K + c * 8);
        }
        CP_COMMIT();
    };

    float acc[4][8][4];
#pragma unroll
    for (int i = 0; i < 4; i++)
#pragma unroll
        for (int j = 0; j < 8; j++)
#pragma unroll
            for (int q = 0; q < 4; q++) acc[i][j][q] = 0.f;

    const int nk = K / KC;
    issue(0, 0); issue(1, 1); issue(2, 2);

    for (int kt = 0; kt < nk; ++kt) {
        const int rem = nk - kt;
        if (rem >= 3)      { CP_WAIT(2); }
        else if (rem == 2) { CP_WAIT(1); }
        else               { CP_WAIT(0); }
        __syncthreads();
        if (kt + 3 < nk) issue(kt + 3, (kt + 3) & 3);

        const char* as = As[kt & 3];
        const char* bs = Bs[kt & 3];
#pragma unroll
        for (int ks = 0; ks < 2; ++ks) {
            uint32_t af[4][4], bf[8][2];
#pragma unroll
            for (int mi = 0; mi < 4; ++mi) {
                int r = wm * 64 + mi * 16;
                uint2 p1 = *(const uint2*)(as + (r + gid)     * 96 + 32 * ks + 8 * tig);
                uint2 p2 = *(const uint2*)(as + (r + gid + 8) * 96 + 32 * ks + 8 * tig);
                af[mi][0] = p1.x; af[mi][1] = p2.x; af[mi][2] = p1.y; af[mi][3] = p2.y;
            }
#pragma unroll
            for (int ni = 0; ni < 8; ++ni) {
                int c = wn * 64 + ni * 8;
                uint2 q = *(const uint2*)(bs + (c + gid) * 96 + 32 * ks + 8 * tig);
                bf[ni][0] = q.x; bf[ni][1] = q.y;
            }
#pragma unroll
            for (int mi = 0; mi < 4; ++mi)
#pragma unroll
                for (int ni = 0; ni < 8; ++ni)
                    mma_f16(acc[mi][ni], af[mi][0], af[mi][1], af[mi][2], af[mi][3],
                            bf[ni][0], bf[ni][1]);
        }
    }

#pragma unroll
    for (int mi = 0; mi < 4; ++mi) {
        int r0 = bm * 128 + wm * 64 + mi * 16 + gid;
#pragma unroll
        for (int ni = 0; ni < 8; ++ni) {
            int c0 = bn * 128 + wn * 64 + ni * 8 + tig * 2;
            if (mode == 0) {
                *(float2*)&C[(size_t)r0 * N + c0]       = make_float2(acc[mi][ni][0], acc[mi][ni][1]);
                *(float2*)&C[(size_t)(r0 + 8) * N + c0] = make_float2(acc[mi][ni][2], acc[mi][ni][3]);
            } else if (mode == 1) {
                g_vT[(size_t)c0 * SEQ + r0]           = __float2half_rn(acc[mi][ni][0]);
                g_vT[(size_t)(c0 + 1) * SEQ + r0]     = __float2half_rn(acc[mi][ni][1]);
                g_vT[(size_t)c0 * SEQ + r0 + 8]       = __float2half_rn(acc[mi][ni][2]);
                g_vT[(size_t)(c0 + 1) * SEQ + r0 + 8] = __float2half_rn(acc[mi][ni][3]);
            } else {
                __half* dst = (mode == 2) ? g_qh : g_kh;
                int i = (c0 & 127) >> 1;
                float2 t1 = g_tab[r0 * 64 + i];
                float2 t2 = g_tab[(r0 + 8) * 64 + i];
                float a0 = acc[mi][ni][0] * t1.x - acc[mi][ni][1] * t1.y;
                float a1 = acc[mi][ni][0] * t1.y + acc[mi][ni][1] * t1.x;
                float b0 = acc[mi][ni][2] * t2.x - acc[mi][ni][3] * t2.y;
                float b1 = acc[mi][ni][2] * t2.y + acc[mi][ni][3] * t2.x;
                int j  = (c0 >> 1) & 7;
                int dc = (c0 & ~15) + (((j & 3) << 1) | (j >> 2)) * 2;
                *(__half2*)&dst[(size_t)r0 * N + dc]       = __floats2half2_rn(a0, a1);
                *(__half2*)&dst[(size_t)(r0 + 8) * N + dc] = __floats2half2_rn(b0, b1);
            }
        }
    }
}

__global__ void __launch_bounds__(128, 2) gemm_qkv_kernel() {
    extern __shared__ char smem[];
    int bx = blockIdx.x, bm = blockIdx.y;
    const __half* B; int N, bn, mode;
    if (bx < 32)      { B = g_wqh; N = DIM; bn = bx;      mode = 2; }
    else if (bx < 40) { B = g_wkh; N = KVD; bn = bx - 32; mode = 3; }
    else              { B = g_wvh; N = KVD; bn = bx - 40; mode = 1; }
    gemm_body(g_xh, B, nullptr, N, DIM, mode, bm, bn, smem);
}

__global__ void __launch_bounds__(128, 2) gemm_kernel(
    const __half* __restrict__ A, const __half* __restrict__ B,
    float* __restrict__ C, int N, int K)
{
    extern __shared__ char smem[];
    gemm_body(A, B, C, N, K, 0, blockIdx.y, blockIdx.x, smem);
}

// ---------------------------------------------------------------------------
// Flash attention (causal, GQA group=4), fp16 m16n8k16 mma.
// REVERTED to the proven R11 shape: CTA = 128 q-rows x head; kv tile 32;
// 4 warps x 32 q-rows (128 thr), 2 CTAs/SM.
// NEW vs R11: 3-stage K/V^T ring, ONE barrier per iteration
// (CP_WAIT(1) -> __syncthreads -> issue KV(kb+3)), 2 groups in flight.
// Warp w rows [32w,32w+32); kv block d = kb-4qt: skip = (d > w);
// partial mask iff d == w.
// ---------------------------------------------------------------------------
#define SM_Q    0                        // 128 x 256B = 32768
#define SM_K0   32768                    // 3 x (32 x 256B = 8192)
#define SM_P    57344                    // 128 x 40 halfs = 10240
#define SM_VT0  67584                    // 3 x (128 x 40 halfs = 10240)
#define ATTN_SMEM 98304

__global__ void __launch_bounds__(128, 2) attn_kernel() {
    extern __shared__ char sm[];
    char* smQ = sm + SM_Q;
    char* smK[3]  = { sm + SM_K0, sm + SM_K0 + 8192, sm + SM_K0 + 16384 };
    __half* Ps    = (__half*)(sm + SM_P);
    __half* VTs[3] = { (__half*)(sm + SM_VT0), (__half*)(sm + SM_VT0 + 10240),
                       (__half*)(sm + SM_VT0 + 20480) };
    const uint32_t qb_ = smem_u32(smQ);

    const int qt  = 15 - (int)blockIdx.x;      // longest first
    const int h   = blockIdx.y;
    const int kvh = h >> 2;
    const int q0  = qt * 128;
    const int tid = threadIdx.x;
    const int w   = tid >> 5, lane = tid & 31;
    const int gid = lane >> 2, tig = lane & 3;
    const int wr  = w * 32;

    auto issueKV = [&](int kb) {
        int s = kb % 3;
        uint32_t kbase = smem_u32(smK[s]);
        uint32_t vbase = smem_u32(VTs[s]);
#pragma unroll
        for (int i = 0; i < 4; i++) {
            int idx = tid + i * 128;
            int r = idx >> 4, m = idx & 15;
            cp_async16(kbase + r * 256 + ((m ^ ((r & 3) << 1)) << 4),
                       &g_kh[(size_t)(kb * 32 + r) * KVD + kvh * HD + m * 8]);
        }
#pragma unroll
        for (int i = 0; i < 4; i++) {
            int idx = tid + i * 128;
            int r = idx >> 2, c = idx & 3;
            cp_async16(vbase + r * 80 + c * 16,
                       &g_vT[(size_t)(kvh * HD + r) * SEQ + kb * 32 + c * 8]);
        }
        CP_COMMIT();
    };

    // Prologue: Q (group 0), KV0, KV1, KV2 (groups 1-3); nkb >= 4 always.
#pragma unroll
    for (int i = 0; i < 16; i++) {
        int idx = tid + i * 128;
        int r = idx >> 4, m = idx & 15;
        cp_async16(qb_ + r * 256 + ((m ^ ((r & 3) << 1)) << 4),
                   &g_qh[(size_t)(q0 + r) * DIM + h * HD + m * 8]);
    }
    CP_COMMIT();
    const int nkb = 4 * (qt + 1);
    issueKV(0);
    issueKV(1);
    issueKV(2);
    CP_WAIT(2);                                 // Q + KV0 complete
    __syncthreads();

    float o[2][16][4];
#pragma unroll
    for (int m = 0; m < 2; m++)
#pragma unroll
        for (int j = 0; j < 16; j++)
#pragma unroll
            for (int q = 0; q < 4; q++) o[m][j][q] = 0.f;
    float mx[2][2] = {{-1e30f, -1e30f}, {-1e30f, -1e30f}};
    float ls[2][2] = {{0.f, 0.f}, {0.f, 0.f}};

    for (int kb = 0; kb < nkb; ++kb) {
        const int d = kb - 4 * qt;              // >=0 only on diagonal band
        const char* smKc = smK[kb % 3];
        const __half* VTc = VTs[kb % 3];

        const bool skip = (d > w);
        if (!skip) {
            float sc[2][4][4];
#pragma unroll
            for (int m = 0; m < 2; m++)
#pragma unroll
                for (int j = 0; j < 4; j++)
#pragma unroll
                    for (int q = 0; q < 4; q++) sc[m][j][q] = 0.f;

            // Q K^T: k-dim 128 -> 8 k16 steps
#pragma unroll
            for (int ks = 0; ks < 8; ++ks) {
                uint32_t af[2][4], bf[4][2];
#pragma unroll
                for (int m = 0; m < 2; m++) {
                    int r = wr + m * 16 + gid;
                    uint2 p1 = *(const uint2*)(smQ + r * 256 + (((4 * ks + tig) ^ ((r & 3) << 2)) << 3));
                    int r2 = r + 8;
                    uint2 p2 = *(const uint2*)(smQ + r2 * 256 + (((4 * ks + tig) ^ ((r2 & 3) << 2)) << 3));
                    af[m][0] = p1.x; af[m][1] = p2.x; af[m][2] = p1.y; af[m][3] = p2.y;
                }
#pragma unroll
                for (int nt = 0; nt < 4; ++nt) {
                    int c = nt * 8 + gid;
                    uint2 q = *(const uint2*)(smKc + c * 256 + (((4 * ks + tig) ^ ((c & 3) << 2)) << 3));
                    bf[nt][0] = q.x; bf[nt][1] = q.y;
                }
#pragma unroll
                for (int m = 0; m < 2; m++)
#pragma unroll
                    for (int nt = 0; nt < 4; ++nt)
                        mma_f16(sc[m][nt], af[m][0], af[m][1], af[m][2], af[m][3],
                                bf[nt][0], bf[nt][1]);
            }

            const float scale = 0.08838834764831845f;  // 1/sqrt(128)
            if (d == w) {
#pragma unroll
                for (int m = 0; m < 2; m++) {
                    int r1 = m * 16 + gid, r2 = r1 + 8;
#pragma unroll
                    for (int nt = 0; nt < 4; ++nt) {
                        int c0 = nt * 8 + tig * 2;
                        sc[m][nt][0] = (c0     <= r1) ? sc[m][nt][0] * scale : -1e30f;
                        sc[m][nt][1] = (c0 + 1 <= r1) ? sc[m][nt][1] * scale : -1e30f;
                        sc[m][nt][2] = (c0     <= r2) ? sc[m][nt][2] * scale : -1e30f;
                        sc[m][nt][3] = (c0 + 1 <= r2) ? sc[m][nt][3] * scale : -1e30f;
                    }
                }
            } else {
#pragma unroll
                for (int m = 0; m < 2; m++)
#pragma unroll
                    for (int nt = 0; nt < 4; ++nt) {
                        sc[m][nt][0] *= scale; sc[m][nt][1] *= scale;
                        sc[m][nt][2] *= scale; sc[m][nt][3] *= scale;
                    }
            }

#pragma unroll
            for (int m = 0; m < 2; m++) {
                float m1 = -1e30f, m2 = -1e30f;
#pragma unroll
                for (int nt = 0; nt < 4; ++nt) {
                    m1 = fmaxf(m1, fmaxf(sc[m][nt][0], sc[m][nt][1]));
                    m2 = fmaxf(m2, fmaxf(sc[m][nt][2], sc[m][nt][3]));
                }
                m1 = fmaxf(m1, __shfl_xor_sync(0xffffffffu, m1, 1));
                m1 = fmaxf(m1, __shfl_xor_sync(0xffffffffu, m1, 2));
                m2 = fmaxf(m2, __shfl_xor_sync(0xffffffffu, m2, 1));
                m2 = fmaxf(m2, __shfl_xor_sync(0xffffffffu, m2, 2));

                float nm1 = fmaxf(mx[m][0], m1), nm2 = fmaxf(mx[m][1], m2);
                float al1 = __expf(mx[m][0] - nm1), al2 = __expf(mx[m][1] - nm2);
                float sum1 = 0.f, sum2 = 0.f;
#pragma unroll
                for (int nt = 0; nt < 4; ++nt) {
                    sc[m][nt][0] = __expf(sc[m][nt][0] - nm1); sum1 += sc[m][nt][0];
                    sc[m][nt][1] = __expf(sc[m][nt][1] - nm1); sum1 += sc[m][nt][1];
                    sc[m][nt][2] = __expf(sc[m][nt][2] - nm2); sum2 += sc[m][nt][2];
                    sc[m][nt][3] = __expf(sc[m][nt][3] - nm2); sum2 += sc[m][nt][3];
                }
                sum1 += __shfl_xor_sync(0xffffffffu, sum1, 1);
                sum1 += __shfl_xor_sync(0xffffffffu, sum1, 2);
                sum2 += __shfl_xor_sync(0xffffffffu, sum2, 1);
                sum2 += __shfl_xor_sync(0xffffffffu, sum2, 2);

                ls[m][0] = ls[m][0] * al1 + sum1; mx[m][0] = nm1;
                ls[m][1] = ls[m][1] * al2 + sum2; mx[m][1] = nm2;
#pragma unroll
                for (int nt = 0; nt < 16; ++nt) {
                    o[m][nt][0] *= al1; o[m][nt][1] *= al1;
                    o[m][nt][2] *= al2; o[m][nt][3] *= al2;
                }

                // write P (fp16) — warp-private rows, stride 40 halfs
                int rA = wr + m * 16 + gid, rB = rA + 8;
#pragma unroll
                for (int nt = 0; nt < 4; ++nt) {
                    int c0 = nt * 8 + tig * 2;
                    *(__half2*)&Ps[rA * 40 + c0] = __floats2half2_rn(sc[m][nt][0], sc[m][nt][1]);
                    *(__half2*)&Ps[rB * 40 + c0] = __floats2half2_rn(sc[m][nt][2], sc[m][nt][3]);
                }
            }
            __syncwarp();

            // o += P @ V : k-dim 32 -> 2 k16 steps, 16 head-col tiles
#pragma unroll
            for (int ks = 0; ks < 2; ++ks) {
                uint32_t af[2][4];
#pragma unroll
                for (int m = 0; m < 2; m++) {
                    int r = wr + m * 16 + gid;
                    af[m][0] = *(const uint32_t*)&Ps[r * 40 + 16 * ks + 2 * tig];
                    af[m][1] = *(const uint32_t*)&Ps[(r + 8) * 40 + 16 * ks + 2 * tig];
                    af[m][2] = *(const uint32_t*)&Ps[r * 40 + 16 * ks + 2 * tig + 8];
                    af[m][3] = *(const uint32_t*)&Ps[(r + 8) * 40 + 16 * ks + 2 * tig + 8];
                }
#pragma unroll
                for (int nt = 0; nt < 16; ++nt) {
                    int n = nt * 8 + gid;
                    uint32_t b0 = *(const uint32_t*)&VTc[n * 40 + 16 * ks + 2 * tig];
                    uint32_t b1 = *(const uint32_t*)&VTc[n * 40 + 16 * ks + 2 * tig + 8];
#pragma unroll
                    for (int m = 0; m < 2; m++)
                        mma_f16(o[m][nt], af[m][0], af[m][1], af[m][2], af[m][3], b0, b1);
                }
            }
        }

        // iteration epilogue: complete KV(kb+1), make it visible, refill slot kb%3
        if (kb + 1 < nkb) {
            if (kb + 2 < nkb) { CP_WAIT(1); } else { CP_WAIT(0); }
            __syncthreads();                    // visibility of KV(kb+1) + WAR for slot kb%3
            if (kb + 3 < nkb) issueKV(kb + 3);
        }
    }

    // epilogue: fp16 + pair-permute along head dim for the O-GEMM A operand.
#pragma unroll
    for (int m = 0; m < 2; m++) {
        const float inv1 = 1.f / ls[m][0], inv2 = 1.f / ls[m][1];
        const int r1 = q0 + wr + m * 16 + gid;
#pragma unroll
        for (int nt = 0; nt < 16; ++nt) {
            int dst = h * HD + (nt >> 1) * 16 + 4 * tig + 2 * (nt & 1);
            *(__half2*)&g_attnh[(size_t)r1 * DIM + dst] =
                __floats2half2_rn(o[m][nt][0] * inv1, o[m][nt][1] * inv1);
            *(__half2*)&g_attnh[(size_t)(r1 + 8) * DIM + dst] =
                __floats2half2_rn(o[m][nt][2] * inv2, o[m][nt][3] * inv2);
        }
    }
}

// ---------------------------------------------------------------------------
extern "C" void kernel_launch(void* const* d_in, const int* in_sizes, int n_in,
                              void* d_out, int out_size) {
    (void)in_sizes; (void)n_in; (void)out_size;
    const float* x  = (const float*)d_in[0];
    const float* wq = (const float*)d_in[1];
    const float* wk = (const float*)d_in[2];
    const float* wv = (const float*)d_in[3];
    const float* wo = (const float*)d_in[4];
    float* out = (float*)d_out;

    __half *attnh, *woh;
    cudaGetSymbolAddress((void**)&attnh, g_attnh);
    cudaGetSymbolAddress((void**)&woh, g_woh);

    cudaFuncSetAttribute(gemm_qkv_kernel, cudaFuncAttributeMaxDynamicSharedMemorySize, GEMM_SMEM);
    cudaFuncSetAttribute(gemm_kernel, cudaFuncAttributeMaxDynamicSharedMemorySize, GEMM_SMEM);
    cudaFuncSetAttribute(attn_kernel, cudaFuncAttributeMaxDynamicSharedMemorySize, ATTN_SMEM);

    tab_kernel<<<(SEQ * 64 + 255) / 256, 256>>>();
    prep_all_kernel<<<(B4 + 255) / 256, 256>>>(x, wq, wk, wv, wo);

    // Merged Q/K/V projections (Q/K rope-fused fp16, V fp16-transposed)
    gemm_qkv_kernel<<<dim3(48, SEQ / 128), 128, GEMM_SMEM>>>();

    // Attention: 16 q-tiles x 32 heads, 4 warps/CTA, 3-stage single-barrier ring
    attn_kernel<<<dim3(SEQ / 128, NH), 128, ATTN_SMEM>>>();

    // Output projection straight into d_out (fp32 store)
    gemm_kernel<<<dim3(DIM / 128, SEQ / 128), 128, GEMM_SMEM>>>(attnh, woh, out, DIM, DIM);
}

// round 16
// speedup vs baseline: 1.5472x; 1.5472x over previous
#include <cuda_runtime.h>
#include <cuda_fp16.h>
#include <cstdint>
#include <cstdio>

#define SEQ 2048
#define DIM 4096
#define NH 32
#define NKV 8
#define HD 128
#define KVD (NKV*HD)   // 1024

// fp16 operands (no fp32 intermediates)
__device__ __half g_qh[SEQ * DIM];       // 16 MB (rope fused in proj epilogue, pair-permuted)
__device__ __half g_kh[SEQ * KVD];       // 4 MB
__device__ __half g_vT[KVD * SEQ];       // 4 MB  (V transposed: [head col][seq])
__device__ __half g_attnh[SEQ * DIM];    // 16 MB (attn out, pair-permuted)
__device__ __half g_xh[SEQ * DIM];       // 16 MB (prep: fp16 + pair-permute)
__device__ __half g_wqh[DIM * DIM];      // 32 MB
__device__ __half g_wkh[KVD * DIM];      // 8 MB
__device__ __half g_wvh[KVD * DIM];      // 8 MB
__device__ __half g_woh[DIM * DIM];      // 32 MB
__device__ float2 g_tab[SEQ * 64];       // 1 MB rope cos/sin table

__device__ __forceinline__ void mma_f16(float* d,
                                        uint32_t a0, uint32_t a1, uint32_t a2, uint32_t a3,
                                        uint32_t b0, uint32_t b1) {
    asm volatile(
        "mma.sync.aligned.m16n8k16.row.col.f32.f16.f16.f32 "
        "{%0,%1,%2,%3}, {%4,%5,%6,%7}, {%8,%9}, {%0,%1,%2,%3};"
        : "+f"(d[0]), "+f"(d[1]), "+f"(d[2]), "+f"(d[3])
        : "r"(a0), "r"(a1), "r"(a2), "r"(a3), "r"(b0), "r"(b1));
}

__device__ __forceinline__ void cp_async16(uint32_t smem_addr, const void* gptr) {
    asm volatile("cp.async.cg.shared.global [%0], [%1], 16;"
                 :: "r"(smem_addr), "l"(gptr) : "memory");
}
#define CP_COMMIT() asm volatile("cp.async.commit_group;" ::: "memory")
#define CP_WAIT(n)  asm volatile("cp.async.wait_group %0;" :: "n"(n) : "memory")

__device__ __forceinline__ uint32_t smem_u32(const void* p) {
    uint32_t a;
    asm("{ .reg .u64 t; cvta.to.shared.u64 t, %1; cvt.u32.u64 %0, t; }" : "=r"(a) : "l"(p));
    return a;
}

// ---------------------------------------------------------------------------
// RoPE cos/sin table
// ---------------------------------------------------------------------------
__global__ void tab_kernel() {
    int idx = blockIdx.x * blockDim.x + threadIdx.x;
    if (idx >= SEQ * 64) return;
    int i = idx & 63, s = idx >> 6;
    float freq = exp2f(-(float)i * (18.931568569324174f / 64.0f));
    float ang = (float)s * freq;
    float sn, cs;
    sincosf(ang, &sn, &cs);
    g_tab[idx] = make_float2(cs, sn);
}

// ---------------------------------------------------------------------------
// Merged prep: fp32 -> fp16 with pair-permute within each 16-el k-group.
// ---------------------------------------------------------------------------
#define NG_X  (SEQ * DIM / 16)
#define NG_WQ (DIM * DIM / 16)
#define NG_WK (KVD * DIM / 16)
#define B0 NG_X
#define B1 (B0 + NG_WQ)
#define B2 (B1 + NG_WK)
#define B3 (B2 + NG_WK)
#define B4 (B3 + NG_WQ)

__global__ void prep_all_kernel(const float* __restrict__ x,  const float* __restrict__ wq,
                                const float* __restrict__ wk, const float* __restrict__ wv,
                                const float* __restrict__ wo) {
    long g = (long)blockIdx.x * blockDim.x + threadIdx.x;
    if (g >= B4) return;
    const float* src; __half* dst; long l;
    if (g < B0)      { src = x;  dst = g_xh;  l = g; }
    else if (g < B1) { src = wq; dst = g_wqh; l = g - B0; }
    else if (g < B2) { src = wk; dst = g_wkh; l = g - B1; }
    else if (g < B3) { src = wv; dst = g_wvh; l = g - B2; }
    else             { src = wo; dst = g_woh; l = g - B3; }

    const float4* s = (const float4*)src + l * 4;
    float4 f0 = s[0], f1 = s[1], f2 = s[2], f3 = s[3];
    __half2* d = (__half2*)dst + l * 8;
    d[0] = __floats2half2_rn(f0.x, f0.y);
    d[1] = __floats2half2_rn(f2.x, f2.y);
    d[2] = __floats2half2_rn(f0.z, f0.w);
    d[3] = __floats2half2_rn(f2.z, f2.w);
    d[4] = __floats2half2_rn(f1.x, f1.y);
    d[5] = __floats2half2_rn(f3.x, f3.y);
    d[6] = __floats2half2_rn(f1.z, f1.w);
    d[7] = __floats2half2_rn(f3.z, f3.w);
}

// ---------------------------------------------------------------------------
// fp16 GEMM core: CTA 128x128, 4 warps 64x64, KC 32, 4-stage cp.async ring.
// modes: 0 fp32 store; 1 V^T fp16 store; 2/3 rope-fused fp16 Q/K store.
// ---------------------------------------------------------------------------
#define KC 32
#define STG_B (128 * 96)
#define GEMM_SMEM (8 * STG_B)            // 98304 B

__device__ __forceinline__ void gemm_body(
    const __half* __restrict__ A, const __half* __restrict__ B,
    float* __restrict__ C, int N, int K, int mode,
    int bm, int bn, char* smem)
{
    char* As[4]; char* Bs[4];
#pragma unroll
    for (int s = 0; s < 4; s++) {
        As[s] = smem + s * 2 * STG_B;
        Bs[s] = As[s] + STG_B;
    }

    const int tid  = threadIdx.x;
    const int warp = tid >> 5, lane = tid & 31;
    const int gid  = lane >> 2, tig = lane & 3;
    const int wm   = warp >> 1, wn = warp & 1;

    const __half* Ab = A + (size_t)(bm * 128) * K;
    const __half* Bb = B + (size_t)(bn * 128) * K;

    auto issue = [&](int kt, int s) {
        const __half* Ak = Ab + kt * KC;
        const __half* Bk = Bb + kt * KC;
        uint32_t as = smem_u32(As[s]);
        uint32_t bs = smem_u32(Bs[s]);
#pragma unroll
        for (int i = 0; i < 4; i++) {
            int idx = tid + i * 128;
            int r = idx >> 2, c = idx & 3;
            cp_async16(as + r * 96 + c * 16, Ak + (size_t)r * K + c * 8);
        }
#pragma unroll
        for (int i = 0; i < 4; i++) {
            int idx = tid + i * 128;
            int r = idx >> 2, c = idx & 3;
            cp_async16(bs + r * 96 + c * 16, Bk + (size_t)r * K + c * 8);
        }
        CP_COMMIT();
    };

    float acc[4][8][4];
#pragma unroll
    for (int i = 0; i < 4; i++)
#pragma unroll
        for (int j = 0; j < 8; j++)
#pragma unroll
            for (int q = 0; q < 4; q++) acc[i][j][q] = 0.f;

    const int nk = K / KC;
    issue(0, 0); issue(1, 1); issue(2, 2);

    for (int kt = 0; kt < nk; ++kt) {
        const int rem = nk - kt;
        if (rem >= 3)      { CP_WAIT(2); }
        else if (rem == 2) { CP_WAIT(1); }
        else               { CP_WAIT(0); }
        __syncthreads();
        if (kt + 3 < nk) issue(kt + 3, (kt + 3) & 3);

        const char* as = As[kt & 3];
        const char* bs = Bs[kt & 3];
#pragma unroll
        for (int ks = 0; ks < 2; ++ks) {
            uint32_t af[4][4], bf[8][2];
#pragma unroll
            for (int mi = 0; mi < 4; ++mi) {
                int r = wm * 64 + mi * 16;
                uint2 p1 = *(const uint2*)(as + (r + gid)     * 96 + 32 * ks + 8 * tig);
                uint2 p2 = *(const uint2*)(as + (r + gid + 8) * 96 + 32 * ks + 8 * tig);
                af[mi][0] = p1.x; af[mi][1] = p2.x; af[mi][2] = p1.y; af[mi][3] = p2.y;
            }
#pragma unroll
            for (int ni = 0; ni < 8; ++ni) {
                int c = wn * 64 + ni * 8;
                uint2 q = *(const uint2*)(bs + (c + gid) * 96 + 32 * ks + 8 * tig);
                bf[ni][0] = q.x; bf[ni][1] = q.y;
            }
#pragma unroll
            for (int mi = 0; mi < 4; ++mi)
#pragma unroll
                for (int ni = 0; ni < 8; ++ni)
                    mma_f16(acc[mi][ni], af[mi][0], af[mi][1], af[mi][2], af[mi][3],
                            bf[ni][0], bf[ni][1]);
        }
    }

#pragma unroll
    for (int mi = 0; mi < 4; ++mi) {
        int r0 = bm * 128 + wm * 64 + mi * 16 + gid;
#pragma unroll
        for (int ni = 0; ni < 8; ++ni) {
            int c0 = bn * 128 + wn * 64 + ni * 8 + tig * 2;
            if (mode == 0) {
                *(float2*)&C[(size_t)r0 * N + c0]       = make_float2(acc[mi][ni][0], acc[mi][ni][1]);
                *(float2*)&C[(size_t)(r0 + 8) * N + c0] = make_float2(acc[mi][ni][2], acc[mi][ni][3]);
            } else if (mode == 1) {
                g_vT[(size_t)c0 * SEQ + r0]           = __float2half_rn(acc[mi][ni][0]);
                g_vT[(size_t)(c0 + 1) * SEQ + r0]     = __float2half_rn(acc[mi][ni][1]);
                g_vT[(size_t)c0 * SEQ + r0 + 8]       = __float2half_rn(acc[mi][ni][2]);
                g_vT[(size_t)(c0 + 1) * SEQ + r0 + 8] = __float2half_rn(acc[mi][ni][3]);
            } else {
                __half* dst = (mode == 2) ? g_qh : g_kh;
                int i = (c0 & 127) >> 1;
                float2 t1 = g_tab[r0 * 64 + i];
                float2 t2 = g_tab[(r0 + 8) * 64 + i];
                float a0 = acc[mi][ni][0] * t1.x - acc[mi][ni][1] * t1.y;
                float a1 = acc[mi][ni][0] * t1.y + acc[mi][ni][1] * t1.x;
                float b0 = acc[mi][ni][2] * t2.x - acc[mi][ni][3] * t2.y;
                float b1 = acc[mi][ni][2] * t2.y + acc[mi][ni][3] * t2.x;
                int j  = (c0 >> 1) & 7;
                int dc = (c0 & ~15) + (((j & 3) << 1) | (j >> 2)) * 2;
                *(__half2*)&dst[(size_t)r0 * N + dc]       = __floats2half2_rn(a0, a1);
                *(__half2*)&dst[(size_t)(r0 + 8) * N + dc] = __floats2half2_rn(b0, b1);
            }
        }
    }
}

__global__ void __launch_bounds__(128, 2) gemm_qkv_kernel() {
    extern __shared__ char smem[];
    int bx = blockIdx.x, bm = blockIdx.y;
    const __half* B; int N, bn, mode;
    if (bx < 32)      { B = g_wqh; N = DIM; bn = bx;      mode = 2; }
    else if (bx < 40) { B = g_wkh; N = KVD; bn = bx - 32; mode = 3; }
    else              { B = g_wvh; N = KVD; bn = bx - 40; mode = 1; }
    gemm_body(g_xh, B, nullptr, N, DIM, mode, bm, bn, smem);
}

__global__ void __launch_bounds__(128, 2) gemm_kernel(
    const __half* __restrict__ A, const __half* __restrict__ B,
    float* __restrict__ C, int N, int K)
{
    extern __shared__ char smem[];
    gemm_body(A, B, C, N, K, 0, blockIdx.y, blockIdx.x, smem);
}

// ---------------------------------------------------------------------------
// Flash attention (causal, GQA group=4), fp16 m16n8k16 mma.
// R11 proven shape: CTA = 128 q-rows x head; kv tile 32; 4 warps x 32 q-rows.
// Double-buffered K/V^T with one-iteration prefetch. smem 78 KB -> 2 CTAs/SM.
// ---------------------------------------------------------------------------
#define SM_Q    0                        // 128 x 256B = 32768
#define SM_K0   32768                    // 32 x 256B  = 8192
#define SM_K1   40960
#define SM_P    49152                    // 128 x 40 halfs = 10240
#define SM_VT0  59392                    // 128 x 40 halfs = 10240
#define SM_VT1  69632
#define ATTN_SMEM 79872

__global__ void __launch_bounds__(128, 2) attn_kernel() {
    extern __shared__ char sm[];
    char* smQ = sm + SM_Q;
    char* smK[2]  = { sm + SM_K0, sm + SM_K1 };
    __half* Ps    = (__half*)(sm + SM_P);
    __half* VTs[2] = { (__half*)(sm + SM_VT0), (__half*)(sm + SM_VT1) };
    const uint32_t qb_ = smem_u32(smQ);

    const int qt  = 15 - (int)blockIdx.x;      // longest first
    const int h   = blockIdx.y;
    const int kvh = h >> 2;
    const int q0  = qt * 128;
    const int tid = threadIdx.x;
    const int w   = tid >> 5, lane = tid & 31;
    const int gid = lane >> 2, tig = lane & 3;
    const int wr  = w * 32;

    // K/VT tile loader into buffer s
    auto issueKV = [&](int kb, int s) {
        uint32_t kbase = smem_u32(smK[s]);
        uint32_t vbase = smem_u32(VTs[s]);
#pragma unroll
        for (int i = 0; i < 4; i++) {
            int idx = tid + i * 128;
            int r = idx >> 4, m = idx & 15;
            cp_async16(kbase + r * 256 + ((m ^ ((r & 3) << 1)) << 4),
                       &g_kh[(size_t)(kb * 32 + r) * KVD + kvh * HD + m * 8]);
        }
#pragma unroll
        for (int i = 0; i < 4; i++) {
            int idx = tid + i * 128;
            int r = idx >> 2, c = idx & 3;
            cp_async16(vbase + r * 80 + c * 16,
                       &g_vT[(size_t)(kvh * HD + r) * SEQ + kb * 32 + c * 8]);
        }
        CP_COMMIT();
    };

    // Q tile (group 1), then KV tile 0 (group 2)
#pragma unroll
    for (int i = 0; i < 16; i++) {
        int idx = tid + i * 128;
        int r = idx >> 4, m = idx & 15;
        cp_async16(qb_ + r * 256 + ((m ^ ((r & 3) << 1)) << 4),
                   &g_qh[(size_t)(q0 + r) * DIM + h * HD + m * 8]);
    }
    CP_COMMIT();
    issueKV(0, 0);

    float o[2][16][4];
#pragma unroll
    for (int m = 0; m < 2; m++)
#pragma unroll
        for (int j = 0; j < 16; j++)
#pragma unroll
            for (int q = 0; q < 4; q++) o[m][j][q] = 0.f;
    float mx[2][2] = {{-1e30f, -1e30f}, {-1e30f, -1e30f}};
    float ls[2][2] = {{0.f, 0.f}, {0.f, 0.f}};

    const int nkb = 4 * (qt + 1);
    for (int kb = 0; kb < nkb; ++kb) {
        const int s = kb & 1;
        const int d = kb - 4 * qt;
        __syncthreads();                       // WAR: iter kb-1 readers of buf s^1 done
        if (kb + 1 < nkb) {
            issueKV(kb + 1, s ^ 1);            // prefetch next tile
            CP_WAIT(1);                        // buf s (issued last iter) complete
        } else {
            CP_WAIT(0);
        }
        __syncthreads();                       // cross-thread visibility of buf s

        const char* smKc = smK[s];
        const __half* VTc = VTs[s];

        const bool skip = (d > w);
        float sc[2][4][4];
        if (!skip) {
#pragma unroll
            for (int m = 0; m < 2; m++)
#pragma unroll
                for (int j = 0; j < 4; j++)
#pragma unroll
                    for (int q = 0; q < 4; q++) sc[m][j][q] = 0.f;

#pragma unroll
            for (int ks = 0; ks < 8; ++ks) {
                uint32_t af[2][4], bf[4][2];
#pragma unroll
                for (int m = 0; m < 2; m++) {
                    int r = wr + m * 16 + gid;
                    uint2 p1 = *(const uint2*)(smQ + r * 256 + (((4 * ks + tig) ^ ((r & 3) << 2)) << 3));
                    int r2 = r + 8;
                    uint2 p2 = *(const uint2*)(smQ + r2 * 256 + (((4 * ks + tig) ^ ((r2 & 3) << 2)) << 3));
                    af[m][0] = p1.x; af[m][1] = p2.x; af[m][2] = p1.y; af[m][3] = p2.y;
                }
#pragma unroll
                for (int nt = 0; nt < 4; ++nt) {
                    int c = nt * 8 + gid;
                    uint2 q = *(const uint2*)(smKc + c * 256 + (((4 * ks + tig) ^ ((c & 3) << 2)) << 3));
                    bf[nt][0] = q.x; bf[nt][1] = q.y;
                }
#pragma unroll
                for (int m = 0; m < 2; m++)
#pragma unroll
                    for (int nt = 0; nt < 4; ++nt)
                        mma_f16(sc[m][nt], af[m][0], af[m][1], af[m][2], af[m][3],
                                bf[nt][0], bf[nt][1]);
            }

            const float scale = 0.08838834764831845f;  // 1/sqrt(128)
            if (d == w) {
#pragma unroll
                for (int m = 0; m < 2; m++) {
                    int r1 = m * 16 + gid, r2 = r1 + 8;
#pragma unroll
                    for (int nt = 0; nt < 4; ++nt) {
                        int c0 = nt * 8 + tig * 2;
                        sc[m][nt][0] = (c0     <= r1) ? sc[m][nt][0] * scale : -1e30f;
                        sc[m][nt][1] = (c0 + 1 <= r1) ? sc[m][nt][1] * scale : -1e30f;
                        sc[m][nt][2] = (c0     <= r2) ? sc[m][nt][2] * scale : -1e30f;
                        sc[m][nt][3] = (c0 + 1 <= r2) ? sc[m][nt][3] * scale : -1e30f;
                    }
                }
            } else {
#pragma unroll
                for (int m = 0; m < 2; m++)
#pragma unroll
                    for (int nt = 0; nt < 4; ++nt) {
                        sc[m][nt][0] *= scale; sc[m][nt][1] *= scale;
                        sc[m][nt][2] *= scale; sc[m][nt][3] *= scale;
                    }
            }

#pragma unroll
            for (int m = 0; m < 2; m++) {
                float m1 = -1e30f, m2 = -1e30f;
#pragma unroll
                for (int nt = 0; nt < 4; ++nt) {
                    m1 = fmaxf(m1, fmaxf(sc[m][nt][0], sc[m][nt][1]));
                    m2 = fmaxf(m2, fmaxf(sc[m][nt][2], sc[m][nt][3]));
                }
                m1 = fmaxf(m1, __shfl_xor_sync(0xffffffffu, m1, 1));
                m1 = fmaxf(m1, __shfl_xor_sync(0xffffffffu, m1, 2));
                m2 = fmaxf(m2, __shfl_xor_sync(0xffffffffu, m2, 1));
                m2 = fmaxf(m2, __shfl_xor_sync(0xffffffffu, m2, 2));

                float nm1 = fmaxf(mx[m][0], m1), nm2 = fmaxf(mx[m][1], m2);
                float al1 = __expf(mx[m][0] - nm1), al2 = __expf(mx[m][1] - nm2);
                float sum1 = 0.f, sum2 = 0.f;
#pragma unroll
                for (int nt = 0; nt < 4; ++nt) {
                    sc[m][nt][0] = __expf(sc[m][nt][0] - nm1); sum1 += sc[m][nt][0];
                    sc[m][nt][1] = __expf(sc[m][nt][1] - nm1); sum1 += sc[m][nt][1];
                    sc[m][nt][2] = __expf(sc[m][nt][2] - nm2); sum2 += sc[m][nt][2];
                    sc[m][nt][3] = __expf(sc[m][nt][3] - nm2); sum2 += sc[m][nt][3];
                }
                sum1 += __shfl_xor_sync(0xffffffffu, sum1, 1);
                sum1 += __shfl_xor_sync(0xffffffffu, sum1, 2);
                sum2 += __shfl_xor_sync(0xffffffffu, sum2, 1);
                sum2 += __shfl_xor_sync(0xffffffffu, sum2, 2);

                ls[m][0] = ls[m][0] * al1 + sum1; mx[m][0] = nm1;
                ls[m][1] = ls[m][1] * al2 + sum2; mx[m][1] = nm2;
#pragma unroll
                for (int nt = 0; nt < 16; ++nt) {
                    o[m][nt][0] *= al1; o[m][nt][1] *= al1;
                    o[m][nt][2] *= al2; o[m][nt][3] *= al2;
                }

                int rA = wr + m * 16 + gid, rB = rA + 8;
#pragma unroll
                for (int nt = 0; nt < 4; ++nt) {
                    int c0 = nt * 8 + tig * 2;
                    *(__half2*)&Ps[rA * 40 + c0] = __floats2half2_rn(sc[m][nt][0], sc[m][nt][1]);
                    *(__half2*)&Ps[rB * 40 + c0] = __floats2half2_rn(sc[m][nt][2], sc[m][nt][3]);
                }
            }
            __syncwarp();

#pragma unroll
            for (int ks = 0; ks < 2; ++ks) {
                uint32_t af[2][4];
#pragma unroll
                for (int m = 0; m < 2; m++) {
                    int r = wr + m * 16 + gid;
                    af[m][0] = *(const uint32_t*)&Ps[r * 40 + 16 * ks + 2 * tig];
                    af[m][1] = *(const uint32_t*)&Ps[(r + 8) * 40 + 16 * ks + 2 * tig];
                    af[m][2] = *(const uint32_t*)&Ps[r * 40 + 16 * ks + 2 * tig + 8];
                    af[m][3] = *(const uint32_t*)&Ps[(r + 8) * 40 + 16 * ks + 2 * tig + 8];
                }
#pragma unroll
                for (int nt = 0; nt < 16; ++nt) {
                    int n = nt * 8 + gid;
                    uint32_t b0 = *(const uint32_t*)&VTc[n * 40 + 16 * ks + 2 * tig];
                    uint32_t b1 = *(const uint32_t*)&VTc[n * 40 + 16 * ks + 2 * tig + 8];
#pragma unroll
                    for (int m = 0; m < 2; m++)
                        mma_f16(o[m][nt], af[m][0], af[m][1], af[m][2], af[m][3], b0, b1);
                }
            }
        }
    }

    // epilogue: fp16 + pair-permute along head dim for the O-GEMM A operand.
#pragma unroll
    for (int m = 0; m < 2; m++) {
        const float inv1 = 1.f / ls[m][0], inv2 = 1.f / ls[m][1];
        const int r1 = q0 + wr + m * 16 + gid;
#pragma unroll
        for (int nt = 0; nt < 16; ++nt) {
            int dst = h * HD + (nt >> 1) * 16 + 4 * tig + 2 * (nt & 1);
            *(__half2*)&g_attnh[(size_t)r1 * DIM + dst] =
                __floats2half2_rn(o[m][nt][0] * inv1, o[m][nt][1] * inv1);
            *(__half2*)&g_attnh[(size_t)(r1 + 8) * DIM + dst] =
                __floats2half2_rn(o[m][nt][2] * inv2, o[m][nt][3] * inv2);
        }
    }
}

// ---------------------------------------------------------------------------
extern "C" void kernel_launch(void* const* d_in, const int* in_sizes, int n_in,
                              void* d_out, int out_size) {
    (void)in_sizes; (void)n_in; (void)out_size;
    const float* x  = (const float*)d_in[0];
    const float* wq = (const float*)d_in[1];
    const float* wk = (const float*)d_in[2];
    const float* wv = (const float*)d_in[3];
    const float* wo = (const float*)d_in[4];
    float* out = (float*)d_out;

    __half *attnh, *woh;
    cudaGetSymbolAddress((void**)&attnh, g_attnh);
    cudaGetSymbolAddress((void**)&woh, g_woh);

    cudaFuncSetAttribute(gemm_qkv_kernel, cudaFuncAttributeMaxDynamicSharedMemorySize, GEMM_SMEM);
    cudaFuncSetAttribute(gemm_kernel, cudaFuncAttributeMaxDynamicSharedMemorySize, GEMM_SMEM);
    cudaFuncSetAttribute(attn_kernel, cudaFuncAttributeMaxDynamicSharedMemorySize, ATTN_SMEM);

    tab_kernel<<<(SEQ * 64 + 255) / 256, 256>>>();
    prep_all_kernel<<<(B4 + 255) / 256, 256>>>(x, wq, wk, wv, wo);

    // Merged Q/K/V projections (Q/K rope-fused fp16, V fp16-transposed)
    gemm_qkv_kernel<<<dim3(48, SEQ / 128), 128, GEMM_SMEM>>>();

    // Attention: 16 q-tiles x 32 heads, double-buffered K/V prefetch
    attn_kernel<<<dim3(SEQ / 128, NH), 128, ATTN_SMEM>>>();

    // Output projection straight into d_out (fp32 store)
    gemm_kernel<<<dim3(DIM / 128, SEQ / 128), 128, GEMM_SMEM>>>(attnh, woh, out, DIM, DIM);
}